// round 2
// baseline (speedup 1.0000x reference)
#include <cuda_runtime.h>
#include <cstdint>
#include <cstddef>

#define BATCH 64
#define NSENT 1024
#define NENT  256
#define DIM   512
#define NEGV  (-1e9f)

// ---------------- scratch (device globals; no allocation allowed) ----------
__device__ float g_query[BATCH * DIM];
__device__ float g_qs[BATCH * DIM];
__device__ float g_qa[BATCH * DIM];
__device__ float g_ctx[BATCH * DIM];
__device__ float g_bias[BATCH * DIM];
__device__ float g_sidefeat[(size_t)BATCH * NENT * DIM];   // 33.5 MB
__device__ float g_escore_part[4 * BATCH * NENT];          // per n-tile partials
__device__ float g_score_part[4 * BATCH * NSENT];

// ---------------- helpers ---------------------------------------------------
__device__ __forceinline__ float sigmoidf_(float x) { return 1.f / (1.f + expf(-x)); }

__device__ __forceinline__ unsigned long long pack_dup(float x) {
    unsigned long long r;
    asm("mov.b64 %0, {%1, %1};" : "=l"(r) : "f"(x));
    return r;
}
__device__ __forceinline__ void fma2(unsigned long long& d,
                                     unsigned long long a,
                                     unsigned long long b) {
    asm("fma.rn.f32x2 %0, %1, %2, %0;" : "+l"(d) : "l"(a), "l"(b));
}
__device__ __forceinline__ void unpack2(float& lo, float& hi, unsigned long long v) {
    asm("mov.b64 {%0, %1}, %2;" : "=f"(lo), "=f"(hi) : "l"(v));
}

__device__ __forceinline__ float warp_sum(float v) {
    #pragma unroll
    for (int o = 16; o; o >>= 1) v += __shfl_xor_sync(0xffffffffu, v, o);
    return v;
}

// ---------------- K1: LSTM single step (h0=c0=0 -> f gate dead) -------------
__global__ void lstm_kernel(const float* __restrict__ x,
                            const float* __restrict__ wih,
                            const float* __restrict__ bih,
                            const float* __restrict__ bhh) {
    int b = blockIdx.x;
    __shared__ float xs[DIM];
    for (int i = threadIdx.x; i < DIM; i += blockDim.x) xs[i] = x[b * DIM + i];
    __syncthreads();
    int warp = threadIdx.x >> 5, lane = threadIdx.x & 31;
    for (int h = warp; h < DIM; h += 8) {
        const float* wi = wih + (size_t)h * DIM;
        const float* wg = wih + (size_t)(1024 + h) * DIM;
        const float* wo = wih + (size_t)(1536 + h) * DIM;
        float si = 0.f, sg = 0.f, so = 0.f;
        for (int d = lane * 4; d < DIM; d += 128) {
            float4 xv = *(const float4*)&xs[d];
            float4 a = *(const float4*)&wi[d];
            float4 g = *(const float4*)&wg[d];
            float4 o = *(const float4*)&wo[d];
            si += xv.x * a.x + xv.y * a.y + xv.z * a.z + xv.w * a.w;
            sg += xv.x * g.x + xv.y * g.y + xv.z * g.z + xv.w * g.w;
            so += xv.x * o.x + xv.y * o.y + xv.z * o.z + xv.w * o.w;
        }
        si = warp_sum(si); sg = warp_sum(sg); so = warp_sum(so);
        if (lane == 0) {
            si += bih[h] + bhh[h];
            sg += bih[1024 + h] + bhh[1024 + h];
            so += bih[1536 + h] + bhh[1536 + h];
            float c = sigmoidf_(si) * tanhf(sg);
            g_query[b * DIM + h] = sigmoidf_(so) * tanhf(c);
        }
    }
}

// ---------------- K2/K5: small projections  out[b,h] = src[b,:] @ W[:,h] (+add)
// mode 0: g_query @ W -> g_qs     mode 1: g_query @ W -> g_qa
// mode 2: g_ctx @ W + g_qa -> g_bias
__global__ void proj_kernel(const float* __restrict__ W, int mode) {
    int b = blockIdx.x;
    int h = threadIdx.x;  // 512 threads
    __shared__ float s[DIM];
    s[h] = (mode == 2) ? g_ctx[b * DIM + h] : g_query[b * DIM + h];
    __syncthreads();
    float acc = (mode == 2) ? g_qa[b * DIM + h] : 0.f;
    const float* Wp = W + h;
    #pragma unroll 8
    for (int d = 0; d < DIM; d++) acc = fmaf(s[d], Wp[(size_t)d * DIM], acc);
    float* out = (mode == 0) ? g_qs : (mode == 1) ? g_qa : g_bias;
    out[b * DIM + h] = acc;
}

// ---------------- K3/K6: fused GEMM + tanh-reduce ---------------------------
// MODE 0: A=entity_mem (R=NENT), W=side_wm, bias=g_qs, v=side_v,
//         store feat -> g_sidefeat, score partials -> g_escore_part
// MODE 1: A=sent_mem (R=NSENT),  W=attn_wm, bias=g_bias, v=attn_v,
//         score partials -> g_score_part
// Block tile 128(m) x 128(n), BK=8, 256 threads, 8x8 microtile via f32x2.
template <int MODE>
__global__ __launch_bounds__(256, 2)
void gemm_fused(const float* __restrict__ A, const float* __restrict__ W,
                const float* __restrict__ vvec) {
    constexpr int R = (MODE == 0) ? NENT : NSENT;
    __shared__ float As[2][8][128];
    __shared__ float Bs[2][8][128];

    int b  = blockIdx.z;
    int m0 = blockIdx.x * 128;
    int n0 = blockIdx.y * 128;
    const float* Ab = A + ((size_t)b * R + m0) * DIM;

    int tid = threadIdx.x;
    int tx = tid & 15, ty = tid >> 4;
    int lr = tid >> 1, lk = (tid & 1) * 4;        // A tile loaders
    int wk = tid >> 5, wn = (tid & 31) * 4;       // B tile loaders

    unsigned long long acc2[4][8];
    #pragma unroll
    for (int i = 0; i < 4; i++)
        #pragma unroll
        for (int j = 0; j < 8; j++) acc2[i][j] = 0ull;

    float4 ar = *(const float4*)(Ab + (size_t)lr * DIM + lk);
    float4 br = *(const float4*)(W + (size_t)wk * DIM + n0 + wn);
    As[0][lk + 0][lr] = ar.x; As[0][lk + 1][lr] = ar.y;
    As[0][lk + 2][lr] = ar.z; As[0][lk + 3][lr] = ar.w;
    *(float4*)&Bs[0][wk][wn] = br;
    __syncthreads();

    #pragma unroll 1
    for (int kt = 0; kt < 64; kt++) {
        int cur = kt & 1;
        if (kt < 63) {
            int k0 = (kt + 1) * 8;
            ar = *(const float4*)(Ab + (size_t)lr * DIM + k0 + lk);
            br = *(const float4*)(W + (size_t)(k0 + wk) * DIM + n0 + wn);
        }
        #pragma unroll
        for (int k = 0; k < 8; k++) {
            ulonglong2 aA = *(const ulonglong2*)&As[cur][k][ty * 8];
            ulonglong2 aB = *(const ulonglong2*)&As[cur][k][ty * 8 + 4];
            float4 b0 = *(const float4*)&Bs[cur][k][tx * 8];
            float4 b1 = *(const float4*)&Bs[cur][k][tx * 8 + 4];
            unsigned long long av[4] = {aA.x, aA.y, aB.x, aB.y};
            unsigned long long bd[8] = {
                pack_dup(b0.x), pack_dup(b0.y), pack_dup(b0.z), pack_dup(b0.w),
                pack_dup(b1.x), pack_dup(b1.y), pack_dup(b1.z), pack_dup(b1.w)};
            #pragma unroll
            for (int mp = 0; mp < 4; mp++)
                #pragma unroll
                for (int n = 0; n < 8; n++) fma2(acc2[mp][n], av[mp], bd[n]);
        }
        if (kt < 63) {
            int nx = (kt & 1) ^ 1;
            As[nx][lk + 0][lr] = ar.x; As[nx][lk + 1][lr] = ar.y;
            As[nx][lk + 2][lr] = ar.z; As[nx][lk + 3][lr] = ar.w;
            *(float4*)&Bs[nx][wk][wn] = br;
            __syncthreads();
        }
    }

    // ---- epilogue: tanh(feat + bias[n]) * v[n], reduce over n ----
    float accf[8][8];
    #pragma unroll
    for (int mp = 0; mp < 4; mp++)
        #pragma unroll
        for (int n = 0; n < 8; n++)
            unpack2(accf[2 * mp][n], accf[2 * mp + 1][n], acc2[mp][n]);

    const float* bv = (MODE == 0) ? &g_qs[b * DIM] : &g_bias[b * DIM];
    float bvr[8], vvr[8];
    #pragma unroll
    for (int n = 0; n < 8; n++) {
        int nn = n0 + tx * 8 + n;
        bvr[n] = bv[nn];
        vvr[n] = vvec[nn];
    }
    float* spart = (MODE == 0) ? g_escore_part : g_score_part;

    #pragma unroll
    for (int m = 0; m < 8; m++) {
        if (MODE == 0) {
            size_t off = ((size_t)b * R + m0 + ty * 8 + m) * DIM + n0 + tx * 8;
            float4 f0 = make_float4(accf[m][0], accf[m][1], accf[m][2], accf[m][3]);
            float4 f1 = make_float4(accf[m][4], accf[m][5], accf[m][6], accf[m][7]);
            *(float4*)&g_sidefeat[off]     = f0;
            *(float4*)&g_sidefeat[off + 4] = f1;
        }
        float s = 0.f;
        #pragma unroll
        for (int n = 0; n < 8; n++) s += tanhf(accf[m][n] + bvr[n]) * vvr[n];
        #pragma unroll
        for (int o = 8; o; o >>= 1) s += __shfl_down_sync(0xffffffffu, s, o, 16);
        if (tx == 0)
            spart[((size_t)blockIdx.y * BATCH + b) * R + m0 + ty * 8 + m] = s;
    }
}

// ---------------- K4: masked softmax over entities + ctx reduction ----------
__global__ void softmax_ctx_kernel(const int* __restrict__ entity_nums) {
    int b = blockIdx.x;
    int tid = threadIdx.x;  // 256 threads == NENT
    __shared__ float attn[NENT];
    __shared__ float red[8];

    int n = entity_nums[b];
    float v = g_escore_part[(0 * BATCH + b) * NENT + tid]
            + g_escore_part[(1 * BATCH + b) * NENT + tid]
            + g_escore_part[(2 * BATCH + b) * NENT + tid]
            + g_escore_part[(3 * BATCH + b) * NENT + tid];
    if (tid >= n) v = NEGV;

    // block max
    float m = v;
    #pragma unroll
    for (int o = 16; o; o >>= 1) m = fmaxf(m, __shfl_xor_sync(0xffffffffu, m, o));
    if ((tid & 31) == 0) red[tid >> 5] = m;
    __syncthreads();
    float M = red[0];
    #pragma unroll
    for (int i = 1; i < 8; i++) M = fmaxf(M, red[i]);
    __syncthreads();

    float e = expf(v - M);
    float s = warp_sum(e);
    if ((tid & 31) == 0) red[tid >> 5] = s;
    __syncthreads();
    float S = red[0];
    #pragma unroll
    for (int i = 1; i < 8; i++) S += red[i];
    attn[tid] = e / S;
    __syncthreads();

    // ctx[b,h] = sum_e attn[e] * side_feat[b,e,h]
    const float* fb = g_sidefeat + (size_t)b * NENT * DIM;
    for (int h = tid; h < DIM; h += 256) {
        float acc = 0.f;
        #pragma unroll 8
        for (int e2 = 0; e2 < NENT; e2++)
            acc = fmaf(attn[e2], fb[(size_t)e2 * DIM + h], acc);
        g_ctx[b * DIM + h] = acc;
    }
}

// ---------------- K7: finalize (sum partials + mask) ------------------------
__global__ void finalize_kernel(const int* __restrict__ sent_nums,
                                float* __restrict__ out) {
    int i = blockIdx.x * 256 + threadIdx.x;  // 65536 total
    int b = i >> 10, s = i & 1023;
    float v = g_score_part[(0 * BATCH + b) * NSENT + s]
            + g_score_part[(1 * BATCH + b) * NSENT + s]
            + g_score_part[(2 * BATCH + b) * NSENT + s]
            + g_score_part[(3 * BATCH + b) * NSENT + s];
    out[i] = (s < sent_nums[b]) ? v : NEGV;
}

// ---------------- launch -----------------------------------------------------
extern "C" void kernel_launch(void* const* d_in, const int* in_sizes, int n_in,
                              void* d_out, int out_size) {
    const float* sent_mem    = (const float*)d_in[0];
    const float* entity_mem  = (const float*)d_in[1];
    const float* ptr_in      = (const float*)d_in[2];
    const int*   sent_nums   = (const int*)d_in[3];
    const int*   entity_nums = (const int*)d_in[4];
    const float* lstm_w_ih   = (const float*)d_in[5];
    // d_in[6] = lstm_w_hh unused (h0 = 0)
    const float* lstm_b_ih   = (const float*)d_in[7];
    const float* lstm_b_hh   = (const float*)d_in[8];
    const float* attn_wm     = (const float*)d_in[9];
    const float* attn_wq     = (const float*)d_in[10];
    const float* attn_v      = (const float*)d_in[11];
    const float* side_wm     = (const float*)d_in[12];
    const float* side_wq     = (const float*)d_in[13];
    const float* side_v      = (const float*)d_in[14];
    const float* attn_ws     = (const float*)d_in[15];
    float* out = (float*)d_out;

    lstm_kernel<<<BATCH, 256>>>(ptr_in, lstm_w_ih, lstm_b_ih, lstm_b_hh);
    proj_kernel<<<BATCH, 512>>>(side_wq, 0);  // g_qs
    proj_kernel<<<BATCH, 512>>>(attn_wq, 1);  // g_qa
    gemm_fused<0><<<dim3(NENT / 128, 4, BATCH), 256>>>(entity_mem, side_wm, side_v);
    softmax_ctx_kernel<<<BATCH, 256>>>(entity_nums);
    proj_kernel<<<BATCH, 512>>>(attn_ws, 2);  // g_bias = g_qa + ctx@attn_ws
    gemm_fused<1><<<dim3(NSENT / 128, 4, BATCH), 256>>>(sent_mem, attn_wm, attn_v);
    finalize_kernel<<<BATCH * NSENT / 256, 256>>>(sent_nums, out);
}